// round 14
// baseline (speedup 1.0000x reference)
#include <cuda_runtime.h>
#include <math.h>

#define B_NUM 8
#define A_NUM 120000
#define C_NUM 80
#define M_NUM 32

#define ALPHA 0.25f
// (1-ALPHA) * p^2 * (-ln(1-p)) == NEG_SCALE * p^2 * log2(1-p)
#define NEG_SCALE (-0.75f * 0.6931471805599453f)

// zero-initialized at module load; the finalize block resets them after each
// run, so every launch (correctness call and each graph replay) starts clean.
__device__ double g_cls_sum[B_NUM];
__device__ double g_reg_sum[B_NUM];
__device__ int    g_num_pos[B_NUM];
__device__ int    g_done;

// ===========================================================================
// Single fused kernel: grid (A/320, 8) x 320 threads.
// Phase 2's first batch is PREFETCHED before phase 1 runs, and the phase-2
// loop is explicitly double-buffered (batch j+1's 4 LDG.128 issue before
// batch j's math) so DRAM latency stays covered. launch_bounds(...,4) gives
// ptxas a 51-reg budget for the two 16-reg batch buffers.
// ===========================================================================
#define FUS_THREADS 320
#define FUS_APB     320
#define FUS_TRIPS   (FUS_APB / 16)                // 20 rows-of-16 per block
#define FUS_BLOCKS  ((A_NUM / FUS_APB) * B_NUM)   // 3000
static_assert(A_NUM % FUS_APB == 0, "exact tiling");
static_assert(FUS_TRIPS % 4 == 0, "unroll batch");

__global__ void __launch_bounds__(FUS_THREADS, 4)
fused_kernel(const float* __restrict__ cls,
             const float* __restrict__ regressions,
             const float* __restrict__ anchors,
             const float* __restrict__ annotations,
             float* out, int out_size) {
    const int b = blockIdx.y;
    const int a_base = blockIdx.x * FUS_APB;

    __shared__ float  s_raw[M_NUM * 5];
    __shared__ float4 s_box[M_NUM];
    __shared__ float2 s_al[M_NUM];              // (area, label)
    __shared__ int    s_cnt;
    __shared__ float  s_mult[FUS_APB];          // 0.0 = ignore row, 1.0 = count row
    __shared__ float  s_wred[FUS_THREADS / 32];
    __shared__ int    s_wcnt[FUS_THREADS / 32];

    // ---- phase-2 geometry + prefetch batch 0 (independent of phase 1) ----
    const int col  = threadIdx.x % 20;
    const int arow = threadIdx.x / 20;
    const float4* __restrict__ p4 =
        (const float4*)(cls + ((size_t)b * A_NUM + a_base) * C_NUM);

    float4 V0 = __ldg(&p4[(0 * 16 + arow) * 20 + col]);
    float4 V1 = __ldg(&p4[(1 * 16 + arow) * 20 + col]);
    float4 V2 = __ldg(&p4[(2 * 16 + arow) * 20 + col]);
    float4 V3 = __ldg(&p4[(3 * 16 + arow) * 20 + col]);

    // ---- stage + compact GTs ----
    if (threadIdx.x < M_NUM * 5)
        s_raw[threadIdx.x] = annotations[b * M_NUM * 5 + threadIdx.x];
    __syncthreads();
    if (threadIdx.x == 0) {
        int cnt = 0;
        for (int m = 0; m < M_NUM; m++) {
            const float* an = &s_raw[m * 5];
            if (an[4] == -1.0f) continue;       // invalid GT -> never matched
            s_box[cnt] = make_float4(an[0], an[1], an[2], an[3]);
            // exact IEEE ops (no FMA contraction)
            s_al[cnt]  = make_float2(
                __fmul_rn(__fsub_rn(an[2], an[0]), __fsub_rn(an[3], an[1])),
                an[4]);
            cnt++;
        }
        s_cnt = cnt;
    }
    __syncthreads();

    // ---- phase 1: one anchor per thread ----
    const int a = a_base + threadIdx.x;
    float4 ab = ((const float4*)anchors)[a];
    float area_a = __fmul_rn(__fsub_rn(ab.z, ab.x), __fsub_rn(ab.w, ab.y));

    float inter_best = -1.0f, ua_best = 1.0f;   // rational running best
    int   arg = 0;
    const int cnt = s_cnt;
    for (int m = 0; m < cnt; m++) {
        float4 g  = s_box[m];
        float  gA = s_al[m].x;
        float iw = fmaxf(__fsub_rn(fminf(ab.z, g.z), fmaxf(ab.x, g.x)), 0.0f);
        float ih = fmaxf(__fsub_rn(fminf(ab.w, g.w), fmaxf(ab.y, g.y)), 0.0f);
        float inter = __fmul_rn(iw, ih);
        float ua = fmaxf(__fsub_rn(__fadd_rn(area_a, gA), inter), 1e-8f);
        // inter/ua > inter_best/ua_best  <=>  inter*ua_best > inter_best*ua
        if (inter * ua_best > inter_best * ua) {
            inter_best = inter; ua_best = ua; arg = m;
        }
    }
    float best = __fdiv_rn(inter_best, ua_best);  // IEEE, threshold-exact

    float reg_s   = 0.0f;
    float pos_fix = 0.0f;   // exact focal correction for this thread's anchor
    int   pos_c   = 0;
    float mult;
    if (best >= 0.5f) {
        float4 g = s_box[arg];
        int cls_id = (int)s_al[arg].y;
        mult = 1.0f;
        {   // exact positive fix-up for element (a, cls_id)
            float x = __ldg(&cls[((size_t)b * A_NUM + a) * C_NUM + cls_id]);
            pos_fix = ALPHA * (1.0f - x) * (1.0f - x) * (-logf(x))
                    - (1.0f - ALPHA) * x * x * (-logf(1.0f - x));
        }
        float aw = __fsub_rn(ab.z, ab.x);
        float ah = __fsub_rn(ab.w, ab.y);
        float acx = ab.x + 0.5f * aw;
        float acy = ab.y + 0.5f * ah;
        float gw = g.z - g.x;
        float gh = g.w - g.y;
        float gcx = g.x + 0.5f * gw;
        float gcy = g.y + 0.5f * gh;
        gw = fmaxf(gw, 1.0f);
        gh = fmaxf(gh, 1.0f);
        float t0 = ((gcx - acx) / aw) / 0.1f;
        float t1 = ((gcy - acy) / ah) / 0.1f;
        float t2 = logf(gw / aw) / 0.2f;
        float t3 = logf(gh / ah) / 0.2f;
        const float* rp = &regressions[((size_t)b * A_NUM + a) * 4];
        float tt[4] = {t0, t1, t2, t3};
        #pragma unroll
        for (int q = 0; q < 4; q++) {
            float diff = fabsf(tt[q] - rp[q]);
            reg_s += (diff <= (1.0f / 9.0f)) ? 4.5f * diff * diff
                                             : diff - (0.5f / 9.0f);
        }
        pos_c = 1;
    } else {
        mult = (best < 0.4f) ? 1.0f : 0.0f;   // negative counts, ignore doesn't
    }
    s_mult[threadIdx.x] = mult;

    // block-reduce reg loss -> one atomic pair per block
    int lane = threadIdx.x & 31;
    int wid  = threadIdx.x >> 5;
    {
        float r = reg_s; int pcr = pos_c;
        #pragma unroll
        for (int o = 16; o > 0; o >>= 1) {
            r   += __shfl_down_sync(0xFFFFFFFFu, r, o);
            pcr += __shfl_down_sync(0xFFFFFFFFu, pcr, o);
        }
        if (lane == 0) { s_wred[wid] = r; s_wcnt[wid] = pcr; }
    }
    __syncthreads();
    if (threadIdx.x == 0) {
        float rs = 0.0f; int pc = 0;
        #pragma unroll
        for (int w = 0; w < FUS_THREADS / 32; w++) { rs += s_wred[w]; pc += s_wcnt[w]; }
        if (pc > 0) {
            atomicAdd(&g_reg_sum[b], (double)rs);
            atomicAdd(&g_num_pos[b], pc);
        }
    }

    // ---- phase 2: double-buffered stream over the block's 320 rows ----
    float neg_acc = 0.0f;   // sum of mult * p^2*log2(1-p)

    #pragma unroll
    for (int j = 0; j < FUS_TRIPS; j += 4) {
        // prefetch next batch before touching this batch's values
        float4 W0, W1, W2, W3;
        if (j + 4 < FUS_TRIPS) {
            W0 = __ldg(&p4[((j + 4) * 16 + arow) * 20 + col]);
            W1 = __ldg(&p4[((j + 5) * 16 + arow) * 20 + col]);
            W2 = __ldg(&p4[((j + 6) * 16 + arow) * 20 + col]);
            W3 = __ldg(&p4[((j + 7) * 16 + arow) * 20 + col]);
        }
        float m0 = s_mult[(j + 0) * 16 + arow];
        float m1 = s_mult[(j + 1) * 16 + arow];
        float m2 = s_mult[(j + 2) * 16 + arow];
        float m3 = s_mult[(j + 3) * 16 + arow];
        // inputs are in (1e-3, 1-1e-3): the reference clamp is an exact no-op
        float t0 =          (V0.x * V0.x) * __log2f(1.0f - V0.x);
        t0 = __fmaf_rn(V0.y * V0.y, __log2f(1.0f - V0.y), t0);
        t0 = __fmaf_rn(V0.z * V0.z, __log2f(1.0f - V0.z), t0);
        t0 = __fmaf_rn(V0.w * V0.w, __log2f(1.0f - V0.w), t0);
        float t1 =          (V1.x * V1.x) * __log2f(1.0f - V1.x);
        t1 = __fmaf_rn(V1.y * V1.y, __log2f(1.0f - V1.y), t1);
        t1 = __fmaf_rn(V1.z * V1.z, __log2f(1.0f - V1.z), t1);
        t1 = __fmaf_rn(V1.w * V1.w, __log2f(1.0f - V1.w), t1);
        float t2 =          (V2.x * V2.x) * __log2f(1.0f - V2.x);
        t2 = __fmaf_rn(V2.y * V2.y, __log2f(1.0f - V2.y), t2);
        t2 = __fmaf_rn(V2.z * V2.z, __log2f(1.0f - V2.z), t2);
        t2 = __fmaf_rn(V2.w * V2.w, __log2f(1.0f - V2.w), t2);
        float t3 =          (V3.x * V3.x) * __log2f(1.0f - V3.x);
        t3 = __fmaf_rn(V3.y * V3.y, __log2f(1.0f - V3.y), t3);
        t3 = __fmaf_rn(V3.z * V3.z, __log2f(1.0f - V3.z), t3);
        t3 = __fmaf_rn(V3.w * V3.w, __log2f(1.0f - V3.w), t3);
        neg_acc = __fmaf_rn(m0, t0, neg_acc);
        neg_acc = __fmaf_rn(m1, t1, neg_acc);
        neg_acc = __fmaf_rn(m2, t2, neg_acc);
        neg_acc = __fmaf_rn(m3, t3, neg_acc);
        V0 = W0; V1 = W1; V2 = W2; V3 = W3;
    }

    float local = pos_fix + NEG_SCALE * neg_acc;

    #pragma unroll
    for (int o = 16; o > 0; o >>= 1)
        local += __shfl_down_sync(0xFFFFFFFFu, local, o);
    __shared__ float warpsum[FUS_THREADS / 32];
    if (lane == 0) warpsum[wid] = local;
    __syncthreads();
    if (wid == 0) {
        float v = (lane < (FUS_THREADS / 32)) ? warpsum[lane] : 0.0f;
        #pragma unroll
        for (int o = 8; o > 0; o >>= 1)
            v += __shfl_down_sync(0xFFFFFFFFu, v, o);
        if (lane == 0) atomicAdd(&g_cls_sum[b], (double)v);
    }

    // ---- finalize: last block computes outputs and resets state ----
    __shared__ int is_last;
    if (threadIdx.x == 0) {
        __threadfence();
        int tkt = atomicAdd(&g_done, 1);
        is_last = (tkt == FUS_BLOCKS - 1);
    }
    __syncthreads();
    if (is_last && wid == 0) {
        __threadfence();   // acquire: see all blocks' atomics
        float cl = 0.0f, rl = 0.0f;
        if (lane < B_NUM) {
            float np = (float)g_num_pos[lane];
            cl = (float)(g_cls_sum[lane]) / fmaxf(np, 1.0f);
            rl = (np > 0.0f)
                   ? (float)(g_reg_sum[lane]) / fmaxf(4.0f * np, 1.0f)
                   : 0.0f;
        }
        #pragma unroll
        for (int o = 4; o > 0; o >>= 1) {
            cl += __shfl_down_sync(0xFFFFFFFFu, cl, o);
            rl += __shfl_down_sync(0xFFFFFFFFu, rl, o);
        }
        if (lane == 0) {
            if (out_size >= 1) out[0] = cl / (float)B_NUM;
            if (out_size >= 2) out[1] = rl / (float)B_NUM;
        }
        // reset accumulators for the next replay
        if (lane < B_NUM) {
            g_cls_sum[lane] = 0.0;
            g_reg_sum[lane] = 0.0;
            g_num_pos[lane] = 0;
        }
        if (lane == 0) g_done = 0;
    }
}

extern "C" void kernel_launch(void* const* d_in, const int* in_sizes, int n_in,
                              void* d_out, int out_size) {
    const float* classifications = (const float*)d_in[0];
    const float* regressions     = (const float*)d_in[1];
    const float* anchors         = (const float*)d_in[2];
    const float* annotations     = (const float*)d_in[3];
    float* out = (float*)d_out;

    dim3 fgrid(A_NUM / FUS_APB, B_NUM);   // 375 x 8 = 3000 blocks
    fused_kernel<<<fgrid, FUS_THREADS>>>(classifications, regressions,
                                         anchors, annotations, out, out_size);
}

// round 15
// speedup vs baseline: 1.5333x; 1.5333x over previous
#include <cuda_runtime.h>
#include <math.h>

#define B_NUM 8
#define A_NUM 120000
#define C_NUM 80
#define M_NUM 32

#define ALPHA 0.25f
// (1-ALPHA) * p^2 * (-ln(1-p)) == NEG_SCALE * p^2 * log2(1-p)
#define NEG_SCALE (-0.75f * 0.6931471805599453f)

// zero-initialized at module load; the finalize block resets them after each
// run, so every launch (correctness call and each graph replay) starts clean.
__device__ double g_cls_sum[B_NUM];
__device__ double g_reg_sum[B_NUM];
__device__ int    g_num_pos[B_NUM];
__device__ int    g_done;

// ===========================================================================
// Single fused kernel: grid (A/320, 8) x 320 threads.  (R13 structure — its
// 32-reg / occ-84% operating point is the proven best; R14 showed that
// trading occupancy for per-warp MLP regresses badly.)
// Phase 1: one anchor per thread — warp-parallel GT compaction (ballot/popc),
//          division-free argmax, one IEEE divide for threshold-exact 0.4/0.5
//          tests; positives compute their exact focal fix-up via one element
//          load and the smooth-L1 terms (kept in registers).
// Phase 2: stream the block's 320 rows (100KB), 16 anchors x 20 cols,
//          4 rows per iteration, branch-free fma accumulation.
// Reduce:  ONE merged shfl pass for (cls local, reg_s, pos_c), one smem
//          round, 3 atomics per block.
// Finalize: ticket pattern — last block writes outputs and resets state.
// ===========================================================================
#define FUS_THREADS 320
#define FUS_APB     320
#define FUS_TRIPS   (FUS_APB / 16)                // 20
#define FUS_BLOCKS  ((A_NUM / FUS_APB) * B_NUM)   // 3000
static_assert(A_NUM % FUS_APB == 0, "exact tiling");
static_assert(FUS_TRIPS % 4 == 0, "unroll batch");
static_assert(M_NUM == 32, "compaction assumes one warp");

__global__ void __launch_bounds__(FUS_THREADS)
fused_kernel(const float* __restrict__ cls,
             const float* __restrict__ regressions,
             const float* __restrict__ anchors,
             const float* __restrict__ annotations,
             float* out, int out_size) {
    const int b = blockIdx.y;
    const int a_base = blockIdx.x * FUS_APB;

    __shared__ float4 s_box[M_NUM];
    __shared__ float2 s_al[M_NUM];              // (area, label)
    __shared__ int    s_cnt;
    __shared__ float  s_mult[FUS_APB];          // 0.0 = ignore row, 1.0 = count
    __shared__ float  s_wcls[FUS_THREADS / 32];
    __shared__ float  s_wreg[FUS_THREADS / 32];
    __shared__ int    s_wcnt[FUS_THREADS / 32];

    // ---- warp-parallel GT stage + compaction (warp 0, lane == GT index) ----
    if (threadIdx.x < 32) {
        const int m = threadIdx.x;
        const float* an = annotations + ((size_t)b * M_NUM + m) * 5;
        float x1 = an[0], y1 = an[1], x2 = an[2], y2 = an[3], lab = an[4];
        bool valid = (lab != -1.0f);            // invalid GT -> never matched
        unsigned msk = __ballot_sync(0xFFFFFFFFu, valid);
        if (valid) {
            int pos = __popc(msk & ((1u << m) - 1));  // order-preserving
            s_box[pos] = make_float4(x1, y1, x2, y2);
            // exact IEEE ops (no FMA contraction)
            s_al[pos]  = make_float2(
                __fmul_rn(__fsub_rn(x2, x1), __fsub_rn(y2, y1)), lab);
        }
        if (m == 0) s_cnt = __popc(msk);
    }
    __syncthreads();

    // ---- phase 1: one anchor per thread ----
    const int a = a_base + threadIdx.x;
    float4 ab = ((const float4*)anchors)[a];
    float area_a = __fmul_rn(__fsub_rn(ab.z, ab.x), __fsub_rn(ab.w, ab.y));

    float inter_best = -1.0f, ua_best = 1.0f;   // rational running best
    int   arg = 0;
    const int cnt = s_cnt;
    for (int m = 0; m < cnt; m++) {
        float4 g  = s_box[m];
        float  gA = s_al[m].x;
        float iw = fmaxf(__fsub_rn(fminf(ab.z, g.z), fmaxf(ab.x, g.x)), 0.0f);
        float ih = fmaxf(__fsub_rn(fminf(ab.w, g.w), fmaxf(ab.y, g.y)), 0.0f);
        float inter = __fmul_rn(iw, ih);
        float ua = fmaxf(__fsub_rn(__fadd_rn(area_a, gA), inter), 1e-8f);
        // inter/ua > inter_best/ua_best  <=>  inter*ua_best > inter_best*ua
        if (inter * ua_best > inter_best * ua) {
            inter_best = inter; ua_best = ua; arg = m;
        }
    }
    float best = __fdiv_rn(inter_best, ua_best);  // IEEE, threshold-exact

    float reg_s   = 0.0f;
    float pos_fix = 0.0f;   // exact focal correction for this thread's anchor
    int   pos_c   = 0;
    float mult;
    if (best >= 0.5f) {
        float4 g = s_box[arg];
        int cls_id = (int)s_al[arg].y;
        mult = 1.0f;
        {   // exact positive fix-up for element (a, cls_id)
            float x = __ldg(&cls[((size_t)b * A_NUM + a) * C_NUM + cls_id]);
            pos_fix = ALPHA * (1.0f - x) * (1.0f - x) * (-logf(x))
                    - (1.0f - ALPHA) * x * x * (-logf(1.0f - x));
        }
        float aw = __fsub_rn(ab.z, ab.x);
        float ah = __fsub_rn(ab.w, ab.y);
        float acx = ab.x + 0.5f * aw;
        float acy = ab.y + 0.5f * ah;
        float gw = g.z - g.x;
        float gh = g.w - g.y;
        float gcx = g.x + 0.5f * gw;
        float gcy = g.y + 0.5f * gh;
        gw = fmaxf(gw, 1.0f);
        gh = fmaxf(gh, 1.0f);
        float t0 = ((gcx - acx) / aw) / 0.1f;
        float t1 = ((gcy - acy) / ah) / 0.1f;
        float t2 = logf(gw / aw) / 0.2f;
        float t3 = logf(gh / ah) / 0.2f;
        const float* rp = &regressions[((size_t)b * A_NUM + a) * 4];
        float tt[4] = {t0, t1, t2, t3};
        #pragma unroll
        for (int q = 0; q < 4; q++) {
            float diff = fabsf(tt[q] - rp[q]);
            reg_s += (diff <= (1.0f / 9.0f)) ? 4.5f * diff * diff
                                             : diff - (0.5f / 9.0f);
        }
        pos_c = 1;
    } else {
        mult = (best < 0.4f) ? 1.0f : 0.0f;   // negative counts, ignore doesn't
    }
    s_mult[threadIdx.x] = mult;
    __syncthreads();   // s_mult visible to all before streaming

    // ---- phase 2: stream this block's 320 rows, branch-free ----
    const int col  = threadIdx.x % 20;
    const int arow = threadIdx.x / 20;
    const float4* __restrict__ p4 =
        (const float4*)(cls + ((size_t)b * A_NUM + a_base) * C_NUM);

    float neg_acc = 0.0f;   // sum of mult * p^2*log2(1-p)

    #pragma unroll 2
    for (int j = 0; j < FUS_TRIPS; j += 4) {
        float4 v0 = __ldg(&p4[((j + 0) * 16 + arow) * 20 + col]);
        float4 v1 = __ldg(&p4[((j + 1) * 16 + arow) * 20 + col]);
        float4 v2 = __ldg(&p4[((j + 2) * 16 + arow) * 20 + col]);
        float4 v3 = __ldg(&p4[((j + 3) * 16 + arow) * 20 + col]);
        float m0 = s_mult[(j + 0) * 16 + arow];
        float m1 = s_mult[(j + 1) * 16 + arow];
        float m2 = s_mult[(j + 2) * 16 + arow];
        float m3 = s_mult[(j + 3) * 16 + arow];
        // inputs are in (1e-3, 1-1e-3): the reference clamp is an exact no-op
        float t0 =          (v0.x * v0.x) * __log2f(1.0f - v0.x);
        t0 = __fmaf_rn(v0.y * v0.y, __log2f(1.0f - v0.y), t0);
        t0 = __fmaf_rn(v0.z * v0.z, __log2f(1.0f - v0.z), t0);
        t0 = __fmaf_rn(v0.w * v0.w, __log2f(1.0f - v0.w), t0);
        float t1 =          (v1.x * v1.x) * __log2f(1.0f - v1.x);
        t1 = __fmaf_rn(v1.y * v1.y, __log2f(1.0f - v1.y), t1);
        t1 = __fmaf_rn(v1.z * v1.z, __log2f(1.0f - v1.z), t1);
        t1 = __fmaf_rn(v1.w * v1.w, __log2f(1.0f - v1.w), t1);
        float t2 =          (v2.x * v2.x) * __log2f(1.0f - v2.x);
        t2 = __fmaf_rn(v2.y * v2.y, __log2f(1.0f - v2.y), t2);
        t2 = __fmaf_rn(v2.z * v2.z, __log2f(1.0f - v2.z), t2);
        t2 = __fmaf_rn(v2.w * v2.w, __log2f(1.0f - v2.w), t2);
        float t3 =          (v3.x * v3.x) * __log2f(1.0f - v3.x);
        t3 = __fmaf_rn(v3.y * v3.y, __log2f(1.0f - v3.y), t3);
        t3 = __fmaf_rn(v3.z * v3.z, __log2f(1.0f - v3.z), t3);
        t3 = __fmaf_rn(v3.w * v3.w, __log2f(1.0f - v3.w), t3);
        neg_acc = __fmaf_rn(m0, t0, neg_acc);
        neg_acc = __fmaf_rn(m1, t1, neg_acc);
        neg_acc = __fmaf_rn(m2, t2, neg_acc);
        neg_acc = __fmaf_rn(m3, t3, neg_acc);
    }

    float local = pos_fix + NEG_SCALE * neg_acc;

    // ---- merged block reduction: (cls local, reg_s, pos_c) in one pass ----
    int lane = threadIdx.x & 31;
    int wid  = threadIdx.x >> 5;
    #pragma unroll
    for (int o = 16; o > 0; o >>= 1) {
        local += __shfl_down_sync(0xFFFFFFFFu, local, o);
        reg_s += __shfl_down_sync(0xFFFFFFFFu, reg_s, o);
        pos_c += __shfl_down_sync(0xFFFFFFFFu, pos_c, o);
    }
    if (lane == 0) { s_wcls[wid] = local; s_wreg[wid] = reg_s; s_wcnt[wid] = pos_c; }
    __syncthreads();
    if (wid == 0) {
        float vc = (lane < (FUS_THREADS / 32)) ? s_wcls[lane] : 0.0f;
        float vr = (lane < (FUS_THREADS / 32)) ? s_wreg[lane] : 0.0f;
        int   vp = (lane < (FUS_THREADS / 32)) ? s_wcnt[lane] : 0;
        #pragma unroll
        for (int o = 8; o > 0; o >>= 1) {
            vc += __shfl_down_sync(0xFFFFFFFFu, vc, o);
            vr += __shfl_down_sync(0xFFFFFFFFu, vr, o);
            vp += __shfl_down_sync(0xFFFFFFFFu, vp, o);
        }
        if (lane == 0) {
            atomicAdd(&g_cls_sum[b], (double)vc);
            if (vp > 0) {
                atomicAdd(&g_reg_sum[b], (double)vr);
                atomicAdd(&g_num_pos[b], vp);
            }
        }
    }

    // ---- finalize: last block computes outputs and resets state ----
    __shared__ int is_last;
    if (threadIdx.x == 0) {
        __threadfence();
        int tkt = atomicAdd(&g_done, 1);
        is_last = (tkt == FUS_BLOCKS - 1);
    }
    __syncthreads();
    if (is_last && wid == 0) {
        __threadfence();   // acquire: see all blocks' atomics
        float cl = 0.0f, rl = 0.0f;
        if (lane < B_NUM) {
            float np = (float)g_num_pos[lane];
            cl = (float)(g_cls_sum[lane]) / fmaxf(np, 1.0f);
            rl = (np > 0.0f)
                   ? (float)(g_reg_sum[lane]) / fmaxf(4.0f * np, 1.0f)
                   : 0.0f;
        }
        #pragma unroll
        for (int o = 4; o > 0; o >>= 1) {
            cl += __shfl_down_sync(0xFFFFFFFFu, cl, o);
            rl += __shfl_down_sync(0xFFFFFFFFu, rl, o);
        }
        if (lane == 0) {
            if (out_size >= 1) out[0] = cl / (float)B_NUM;
            if (out_size >= 2) out[1] = rl / (float)B_NUM;
        }
        // reset accumulators for the next replay
        if (lane < B_NUM) {
            g_cls_sum[lane] = 0.0;
            g_reg_sum[lane] = 0.0;
            g_num_pos[lane] = 0;
        }
        if (lane == 0) g_done = 0;
    }
}

extern "C" void kernel_launch(void* const* d_in, const int* in_sizes, int n_in,
                              void* d_out, int out_size) {
    const float* classifications = (const float*)d_in[0];
    const float* regressions     = (const float*)d_in[1];
    const float* anchors         = (const float*)d_in[2];
    const float* annotations     = (const float*)d_in[3];
    float* out = (float*)d_out;

    dim3 fgrid(A_NUM / FUS_APB, B_NUM);   // 375 x 8 = 3000 blocks
    fused_kernel<<<fgrid, FUS_THREADS>>>(classifications, regressions,
                                         anchors, annotations, out, out_size);
}

// round 16
// speedup vs baseline: 1.6945x; 1.1051x over previous
#include <cuda_runtime.h>
#include <math.h>

#define B_NUM 8
#define A_NUM 120000
#define C_NUM 80
#define M_NUM 32

#define ALPHA 0.25f
// (1-ALPHA) * p^2 * (-ln(1-p)) == NEG_SCALE * p^2 * log2(1-p)
#define NEG_SCALE (-0.75f * 0.6931471805599453f)

// zero-initialized at module load; the finalize block resets them after each
// run, so every launch (correctness call and each graph replay) starts clean.
__device__ double g_cls_sum[B_NUM];
__device__ double g_reg_sum[B_NUM];
__device__ int    g_num_pos[B_NUM];
__device__ int    g_done;

// ===========================================================================
// Single fused kernel: grid (A/320, 8) x 320 threads.
// R15 structure (32-reg / occ-85% operating point) with phase 2 FULLY
// unrolled: all 20 LDG.128 + 20 LDS use immediate offsets — no per-batch
// address IMADs, no loop control. launch_bounds(320,6) pins regs <= 34 so
// the unroll cannot recreate R14's occupancy collapse.
// ===========================================================================
#define FUS_THREADS 320
#define FUS_APB     320
#define FUS_TRIPS   (FUS_APB / 16)                // 20
#define FUS_BLOCKS  ((A_NUM / FUS_APB) * B_NUM)   // 3000
static_assert(A_NUM % FUS_APB == 0, "exact tiling");
static_assert(FUS_TRIPS % 4 == 0, "unroll batch");
static_assert(M_NUM == 32, "compaction assumes one warp");

__global__ void __launch_bounds__(FUS_THREADS, 6)
fused_kernel(const float* __restrict__ cls,
             const float* __restrict__ regressions,
             const float* __restrict__ anchors,
             const float* __restrict__ annotations,
             float* out, int out_size) {
    const int b = blockIdx.y;
    const int a_base = blockIdx.x * FUS_APB;

    __shared__ float4 s_box[M_NUM];
    __shared__ float2 s_al[M_NUM];              // (area, label)
    __shared__ int    s_cnt;
    __shared__ float  s_mult[FUS_APB];          // 0.0 = ignore row, 1.0 = count
    __shared__ float  s_wcls[FUS_THREADS / 32];
    __shared__ float  s_wreg[FUS_THREADS / 32];
    __shared__ int    s_wcnt[FUS_THREADS / 32];

    // ---- warp-parallel GT stage + compaction (warp 0, lane == GT index) ----
    if (threadIdx.x < 32) {
        const int m = threadIdx.x;
        const float* an = annotations + ((size_t)b * M_NUM + m) * 5;
        float x1 = an[0], y1 = an[1], x2 = an[2], y2 = an[3], lab = an[4];
        bool valid = (lab != -1.0f);            // invalid GT -> never matched
        unsigned msk = __ballot_sync(0xFFFFFFFFu, valid);
        if (valid) {
            int pos = __popc(msk & ((1u << m) - 1));  // order-preserving
            s_box[pos] = make_float4(x1, y1, x2, y2);
            // exact IEEE ops (no FMA contraction)
            s_al[pos]  = make_float2(
                __fmul_rn(__fsub_rn(x2, x1), __fsub_rn(y2, y1)), lab);
        }
        if (m == 0) s_cnt = __popc(msk);
    }
    __syncthreads();

    // ---- phase 1: one anchor per thread ----
    const int a = a_base + threadIdx.x;
    float4 ab = ((const float4*)anchors)[a];
    float area_a = __fmul_rn(__fsub_rn(ab.z, ab.x), __fsub_rn(ab.w, ab.y));

    float inter_best = -1.0f, ua_best = 1.0f;   // rational running best
    int   arg = 0;
    const int cnt = s_cnt;
    for (int m = 0; m < cnt; m++) {
        float4 g  = s_box[m];
        float  gA = s_al[m].x;
        float iw = fmaxf(__fsub_rn(fminf(ab.z, g.z), fmaxf(ab.x, g.x)), 0.0f);
        float ih = fmaxf(__fsub_rn(fminf(ab.w, g.w), fmaxf(ab.y, g.y)), 0.0f);
        float inter = __fmul_rn(iw, ih);
        float ua = fmaxf(__fsub_rn(__fadd_rn(area_a, gA), inter), 1e-8f);
        // inter/ua > inter_best/ua_best  <=>  inter*ua_best > inter_best*ua
        if (inter * ua_best > inter_best * ua) {
            inter_best = inter; ua_best = ua; arg = m;
        }
    }
    float best = __fdiv_rn(inter_best, ua_best);  // IEEE, threshold-exact

    float reg_s   = 0.0f;
    float pos_fix = 0.0f;   // exact focal correction for this thread's anchor
    int   pos_c   = 0;
    float mult;
    if (best >= 0.5f) {
        float4 g = s_box[arg];
        int cls_id = (int)s_al[arg].y;
        mult = 1.0f;
        {   // exact positive fix-up for element (a, cls_id)
            float x = __ldg(&cls[((size_t)b * A_NUM + a) * C_NUM + cls_id]);
            pos_fix = ALPHA * (1.0f - x) * (1.0f - x) * (-logf(x))
                    - (1.0f - ALPHA) * x * x * (-logf(1.0f - x));
        }
        float aw = __fsub_rn(ab.z, ab.x);
        float ah = __fsub_rn(ab.w, ab.y);
        float acx = ab.x + 0.5f * aw;
        float acy = ab.y + 0.5f * ah;
        float gw = g.z - g.x;
        float gh = g.w - g.y;
        float gcx = g.x + 0.5f * gw;
        float gcy = g.y + 0.5f * gh;
        gw = fmaxf(gw, 1.0f);
        gh = fmaxf(gh, 1.0f);
        float t0 = ((gcx - acx) / aw) / 0.1f;
        float t1 = ((gcy - acy) / ah) / 0.1f;
        float t2 = logf(gw / aw) / 0.2f;
        float t3 = logf(gh / ah) / 0.2f;
        const float* rp = &regressions[((size_t)b * A_NUM + a) * 4];
        float tt[4] = {t0, t1, t2, t3};
        #pragma unroll
        for (int q = 0; q < 4; q++) {
            float diff = fabsf(tt[q] - rp[q]);
            reg_s += (diff <= (1.0f / 9.0f)) ? 4.5f * diff * diff
                                             : diff - (0.5f / 9.0f);
        }
        pos_c = 1;
    } else {
        mult = (best < 0.4f) ? 1.0f : 0.0f;   // negative counts, ignore doesn't
    }
    s_mult[threadIdx.x] = mult;
    __syncthreads();   // s_mult visible to all before streaming

    // ---- phase 2: stream this block's 320 rows, branch-free, FULL unroll ----
    const int col  = threadIdx.x % 20;
    const int arow = threadIdx.x / 20;
    const float4* __restrict__ p4 =
        (const float4*)(cls + ((size_t)b * A_NUM + a_base) * C_NUM)
        + arow * 20 + col;                     // thread base; offsets are imm
    const float* __restrict__ mp = &s_mult[arow];

    float neg_acc = 0.0f;   // sum of mult * p^2*log2(1-p)

    #pragma unroll
    for (int j = 0; j < FUS_TRIPS; j += 4) {
        float4 v0 = __ldg(p4 + (j + 0) * 320);
        float4 v1 = __ldg(p4 + (j + 1) * 320);
        float4 v2 = __ldg(p4 + (j + 2) * 320);
        float4 v3 = __ldg(p4 + (j + 3) * 320);
        float m0 = mp[(j + 0) * 16];
        float m1 = mp[(j + 1) * 16];
        float m2 = mp[(j + 2) * 16];
        float m3 = mp[(j + 3) * 16];
        // inputs are in (1e-3, 1-1e-3): the reference clamp is an exact no-op
        float t0 =          (v0.x * v0.x) * __log2f(1.0f - v0.x);
        t0 = __fmaf_rn(v0.y * v0.y, __log2f(1.0f - v0.y), t0);
        t0 = __fmaf_rn(v0.z * v0.z, __log2f(1.0f - v0.z), t0);
        t0 = __fmaf_rn(v0.w * v0.w, __log2f(1.0f - v0.w), t0);
        float t1 =          (v1.x * v1.x) * __log2f(1.0f - v1.x);
        t1 = __fmaf_rn(v1.y * v1.y, __log2f(1.0f - v1.y), t1);
        t1 = __fmaf_rn(v1.z * v1.z, __log2f(1.0f - v1.z), t1);
        t1 = __fmaf_rn(v1.w * v1.w, __log2f(1.0f - v1.w), t1);
        float t2 =          (v2.x * v2.x) * __log2f(1.0f - v2.x);
        t2 = __fmaf_rn(v2.y * v2.y, __log2f(1.0f - v2.y), t2);
        t2 = __fmaf_rn(v2.z * v2.z, __log2f(1.0f - v2.z), t2);
        t2 = __fmaf_rn(v2.w * v2.w, __log2f(1.0f - v2.w), t2);
        float t3 =          (v3.x * v3.x) * __log2f(1.0f - v3.x);
        t3 = __fmaf_rn(v3.y * v3.y, __log2f(1.0f - v3.y), t3);
        t3 = __fmaf_rn(v3.z * v3.z, __log2f(1.0f - v3.z), t3);
        t3 = __fmaf_rn(v3.w * v3.w, __log2f(1.0f - v3.w), t3);
        neg_acc = __fmaf_rn(m0, t0, neg_acc);
        neg_acc = __fmaf_rn(m1, t1, neg_acc);
        neg_acc = __fmaf_rn(m2, t2, neg_acc);
        neg_acc = __fmaf_rn(m3, t3, neg_acc);
    }

    float local = pos_fix + NEG_SCALE * neg_acc;

    // ---- merged block reduction: (cls local, reg_s, pos_c) in one pass ----
    int lane = threadIdx.x & 31;
    int wid  = threadIdx.x >> 5;
    #pragma unroll
    for (int o = 16; o > 0; o >>= 1) {
        local += __shfl_down_sync(0xFFFFFFFFu, local, o);
        reg_s += __shfl_down_sync(0xFFFFFFFFu, reg_s, o);
        pos_c += __shfl_down_sync(0xFFFFFFFFu, pos_c, o);
    }
    if (lane == 0) { s_wcls[wid] = local; s_wreg[wid] = reg_s; s_wcnt[wid] = pos_c; }
    __syncthreads();
    if (wid == 0) {
        float vc = (lane < (FUS_THREADS / 32)) ? s_wcls[lane] : 0.0f;
        float vr = (lane < (FUS_THREADS / 32)) ? s_wreg[lane] : 0.0f;
        int   vp = (lane < (FUS_THREADS / 32)) ? s_wcnt[lane] : 0;
        #pragma unroll
        for (int o = 8; o > 0; o >>= 1) {
            vc += __shfl_down_sync(0xFFFFFFFFu, vc, o);
            vr += __shfl_down_sync(0xFFFFFFFFu, vr, o);
            vp += __shfl_down_sync(0xFFFFFFFFu, vp, o);
        }
        if (lane == 0) {
            atomicAdd(&g_cls_sum[b], (double)vc);
            if (vp > 0) {
                atomicAdd(&g_reg_sum[b], (double)vr);
                atomicAdd(&g_num_pos[b], vp);
            }
        }
    }

    // ---- finalize: last block computes outputs and resets state ----
    __shared__ int is_last;
    if (threadIdx.x == 0) {
        __threadfence();
        int tkt = atomicAdd(&g_done, 1);
        is_last = (tkt == FUS_BLOCKS - 1);
    }
    __syncthreads();
    if (is_last && wid == 0) {
        __threadfence();   // acquire: see all blocks' atomics
        float cl = 0.0f, rl = 0.0f;
        if (lane < B_NUM) {
            float np = (float)g_num_pos[lane];
            cl = (float)(g_cls_sum[lane]) / fmaxf(np, 1.0f);
            rl = (np > 0.0f)
                   ? (float)(g_reg_sum[lane]) / fmaxf(4.0f * np, 1.0f)
                   : 0.0f;
        }
        #pragma unroll
        for (int o = 4; o > 0; o >>= 1) {
            cl += __shfl_down_sync(0xFFFFFFFFu, cl, o);
            rl += __shfl_down_sync(0xFFFFFFFFu, rl, o);
        }
        if (lane == 0) {
            if (out_size >= 1) out[0] = cl / (float)B_NUM;
            if (out_size >= 2) out[1] = rl / (float)B_NUM;
        }
        // reset accumulators for the next replay
        if (lane < B_NUM) {
            g_cls_sum[lane] = 0.0;
            g_reg_sum[lane] = 0.0;
            g_num_pos[lane] = 0;
        }
        if (lane == 0) g_done = 0;
    }
}

extern "C" void kernel_launch(void* const* d_in, const int* in_sizes, int n_in,
                              void* d_out, int out_size) {
    const float* classifications = (const float*)d_in[0];
    const float* regressions     = (const float*)d_in[1];
    const float* anchors         = (const float*)d_in[2];
    const float* annotations     = (const float*)d_in[3];
    float* out = (float*)d_out;

    dim3 fgrid(A_NUM / FUS_APB, B_NUM);   // 375 x 8 = 3000 blocks
    fused_kernel<<<fgrid, FUS_THREADS>>>(classifications, regressions,
                                         anchors, annotations, out, out_size);
}

// round 17
// speedup vs baseline: 1.7022x; 1.0046x over previous
#include <cuda_runtime.h>
#include <math.h>

#define B_NUM 8
#define A_NUM 120000
#define C_NUM 80
#define M_NUM 32

#define ALPHA 0.25f
// (1-ALPHA) * p^2 * (-ln(1-p)) == NEG_SCALE * p^2 * log2(1-p)
#define NEG_SCALE (-0.75f * 0.6931471805599453f)

// zero-initialized at module load; the finalize block resets them after each
// run, so every launch (correctness call and each graph replay) starts clean.
__device__ double g_cls_sum[B_NUM];
__device__ double g_reg_sum[B_NUM];
__device__ int    g_num_pos[B_NUM];
__device__ int    g_done;

// ===========================================================================
// Single fused kernel: grid (A/320, 8) x 320 threads.
// R16 structure (32-reg / occ-85%, fully-unrolled phase 2) plus:
//  - GT loop unrolled x4 (batched LDS, 4 independent IoU computations,
//    SEQUENTIAL argmax update preserving first-occurrence semantics)
//  - ternary-select argmax update (FSEL pred-as-data, not 13-cyc guards)
// ===========================================================================
#define FUS_THREADS 320
#define FUS_APB     320
#define FUS_TRIPS   (FUS_APB / 16)                // 20
#define FUS_BLOCKS  ((A_NUM / FUS_APB) * B_NUM)   // 3000
static_assert(A_NUM % FUS_APB == 0, "exact tiling");
static_assert(FUS_TRIPS % 4 == 0, "unroll batch");
static_assert(M_NUM == 32, "compaction assumes one warp");

__global__ void __launch_bounds__(FUS_THREADS, 6)
fused_kernel(const float* __restrict__ cls,
             const float* __restrict__ regressions,
             const float* __restrict__ anchors,
             const float* __restrict__ annotations,
             float* out, int out_size) {
    const int b = blockIdx.y;
    const int a_base = blockIdx.x * FUS_APB;

    __shared__ float4 s_box[M_NUM];
    __shared__ float2 s_al[M_NUM];              // (area, label)
    __shared__ int    s_cnt;
    __shared__ float  s_mult[FUS_APB];          // 0.0 = ignore row, 1.0 = count
    __shared__ float  s_wcls[FUS_THREADS / 32];
    __shared__ float  s_wreg[FUS_THREADS / 32];
    __shared__ int    s_wcnt[FUS_THREADS / 32];

    // ---- warp-parallel GT stage + compaction (warp 0, lane == GT index) ----
    if (threadIdx.x < 32) {
        const int m = threadIdx.x;
        const float* an = annotations + ((size_t)b * M_NUM + m) * 5;
        float x1 = an[0], y1 = an[1], x2 = an[2], y2 = an[3], lab = an[4];
        bool valid = (lab != -1.0f);            // invalid GT -> never matched
        unsigned msk = __ballot_sync(0xFFFFFFFFu, valid);
        if (valid) {
            int pos = __popc(msk & ((1u << m) - 1));  // order-preserving
            s_box[pos] = make_float4(x1, y1, x2, y2);
            // exact IEEE ops (no FMA contraction)
            s_al[pos]  = make_float2(
                __fmul_rn(__fsub_rn(x2, x1), __fsub_rn(y2, y1)), lab);
        }
        if (m == 0) s_cnt = __popc(msk);
    }
    __syncthreads();

    // ---- phase 1: one anchor per thread ----
    const int a = a_base + threadIdx.x;
    float4 ab = ((const float4*)anchors)[a];
    float area_a = __fmul_rn(__fsub_rn(ab.z, ab.x), __fsub_rn(ab.w, ab.y));

    float inter_best = -1.0f, ua_best = 1.0f;   // rational running best
    int   arg = 0;
    const int cnt = s_cnt;

    int m = 0;
    for (; m + 4 <= cnt; m += 4) {
        // batched loads (8 LDS issued together), 4 independent IoU computations
        float4 g0 = s_box[m + 0], g1 = s_box[m + 1];
        float4 g2 = s_box[m + 2], g3 = s_box[m + 3];
        float A0 = s_al[m + 0].x, A1 = s_al[m + 1].x;
        float A2 = s_al[m + 2].x, A3 = s_al[m + 3].x;

        float iw0 = fmaxf(__fsub_rn(fminf(ab.z, g0.z), fmaxf(ab.x, g0.x)), 0.0f);
        float ih0 = fmaxf(__fsub_rn(fminf(ab.w, g0.w), fmaxf(ab.y, g0.y)), 0.0f);
        float in0 = __fmul_rn(iw0, ih0);
        float ua0 = fmaxf(__fsub_rn(__fadd_rn(area_a, A0), in0), 1e-8f);
        float iw1 = fmaxf(__fsub_rn(fminf(ab.z, g1.z), fmaxf(ab.x, g1.x)), 0.0f);
        float ih1 = fmaxf(__fsub_rn(fminf(ab.w, g1.w), fmaxf(ab.y, g1.y)), 0.0f);
        float in1 = __fmul_rn(iw1, ih1);
        float ua1 = fmaxf(__fsub_rn(__fadd_rn(area_a, A1), in1), 1e-8f);
        float iw2 = fmaxf(__fsub_rn(fminf(ab.z, g2.z), fmaxf(ab.x, g2.x)), 0.0f);
        float ih2 = fmaxf(__fsub_rn(fminf(ab.w, g2.w), fmaxf(ab.y, g2.y)), 0.0f);
        float in2 = __fmul_rn(iw2, ih2);
        float ua2 = fmaxf(__fsub_rn(__fadd_rn(area_a, A2), in2), 1e-8f);
        float iw3 = fmaxf(__fsub_rn(fminf(ab.z, g3.z), fmaxf(ab.x, g3.x)), 0.0f);
        float ih3 = fmaxf(__fsub_rn(fminf(ab.w, g3.w), fmaxf(ab.y, g3.y)), 0.0f);
        float in3 = __fmul_rn(iw3, ih3);
        float ua3 = fmaxf(__fsub_rn(__fadd_rn(area_a, A3), in3), 1e-8f);

        // sequential first-occurrence argmax (strict >), ternary/FSEL form
        bool c0 = in0 * ua_best > inter_best * ua0;
        inter_best = c0 ? in0 : inter_best;
        ua_best    = c0 ? ua0 : ua_best;
        arg        = c0 ? (m + 0) : arg;
        bool c1 = in1 * ua_best > inter_best * ua1;
        inter_best = c1 ? in1 : inter_best;
        ua_best    = c1 ? ua1 : ua_best;
        arg        = c1 ? (m + 1) : arg;
        bool c2 = in2 * ua_best > inter_best * ua2;
        inter_best = c2 ? in2 : inter_best;
        ua_best    = c2 ? ua2 : ua_best;
        arg        = c2 ? (m + 2) : arg;
        bool c3 = in3 * ua_best > inter_best * ua3;
        inter_best = c3 ? in3 : inter_best;
        ua_best    = c3 ? ua3 : ua_best;
        arg        = c3 ? (m + 3) : arg;
    }
    for (; m < cnt; m++) {
        float4 g  = s_box[m];
        float  gA = s_al[m].x;
        float iw = fmaxf(__fsub_rn(fminf(ab.z, g.z), fmaxf(ab.x, g.x)), 0.0f);
        float ih = fmaxf(__fsub_rn(fminf(ab.w, g.w), fmaxf(ab.y, g.y)), 0.0f);
        float inter = __fmul_rn(iw, ih);
        float ua = fmaxf(__fsub_rn(__fadd_rn(area_a, gA), inter), 1e-8f);
        bool c = inter * ua_best > inter_best * ua;
        inter_best = c ? inter : inter_best;
        ua_best    = c ? ua : ua_best;
        arg        = c ? m : arg;
    }
    float best = __fdiv_rn(inter_best, ua_best);  // IEEE, threshold-exact

    float reg_s   = 0.0f;
    float pos_fix = 0.0f;   // exact focal correction for this thread's anchor
    int   pos_c   = 0;
    float mult;
    if (best >= 0.5f) {
        float4 g = s_box[arg];
        int cls_id = (int)s_al[arg].y;
        mult = 1.0f;
        {   // exact positive fix-up for element (a, cls_id)
            float x = __ldg(&cls[((size_t)b * A_NUM + a) * C_NUM + cls_id]);
            pos_fix = ALPHA * (1.0f - x) * (1.0f - x) * (-logf(x))
                    - (1.0f - ALPHA) * x * x * (-logf(1.0f - x));
        }
        float aw = __fsub_rn(ab.z, ab.x);
        float ah = __fsub_rn(ab.w, ab.y);
        float acx = ab.x + 0.5f * aw;
        float acy = ab.y + 0.5f * ah;
        float gw = g.z - g.x;
        float gh = g.w - g.y;
        float gcx = g.x + 0.5f * gw;
        float gcy = g.y + 0.5f * gh;
        gw = fmaxf(gw, 1.0f);
        gh = fmaxf(gh, 1.0f);
        float t0 = ((gcx - acx) / aw) / 0.1f;
        float t1 = ((gcy - acy) / ah) / 0.1f;
        float t2 = logf(gw / aw) / 0.2f;
        float t3 = logf(gh / ah) / 0.2f;
        const float* rp = &regressions[((size_t)b * A_NUM + a) * 4];
        float tt[4] = {t0, t1, t2, t3};
        #pragma unroll
        for (int q = 0; q < 4; q++) {
            float diff = fabsf(tt[q] - rp[q]);
            reg_s += (diff <= (1.0f / 9.0f)) ? 4.5f * diff * diff
                                             : diff - (0.5f / 9.0f);
        }
        pos_c = 1;
    } else {
        mult = (best < 0.4f) ? 1.0f : 0.0f;   // negative counts, ignore doesn't
    }
    s_mult[threadIdx.x] = mult;
    __syncthreads();   // s_mult visible to all before streaming

    // ---- phase 2: stream this block's 320 rows, branch-free, FULL unroll ----
    const int col  = threadIdx.x % 20;
    const int arow = threadIdx.x / 20;
    const float4* __restrict__ p4 =
        (const float4*)(cls + ((size_t)b * A_NUM + a_base) * C_NUM)
        + arow * 20 + col;                     // thread base; offsets are imm
    const float* __restrict__ mp = &s_mult[arow];

    float neg_acc = 0.0f;   // sum of mult * p^2*log2(1-p)

    #pragma unroll
    for (int j = 0; j < FUS_TRIPS; j += 4) {
        float4 v0 = __ldg(p4 + (j + 0) * 320);
        float4 v1 = __ldg(p4 + (j + 1) * 320);
        float4 v2 = __ldg(p4 + (j + 2) * 320);
        float4 v3 = __ldg(p4 + (j + 3) * 320);
        float m0 = mp[(j + 0) * 16];
        float m1 = mp[(j + 1) * 16];
        float m2 = mp[(j + 2) * 16];
        float m3 = mp[(j + 3) * 16];
        // inputs are in (1e-3, 1-1e-3): the reference clamp is an exact no-op
        float t0 =          (v0.x * v0.x) * __log2f(1.0f - v0.x);
        t0 = __fmaf_rn(v0.y * v0.y, __log2f(1.0f - v0.y), t0);
        t0 = __fmaf_rn(v0.z * v0.z, __log2f(1.0f - v0.z), t0);
        t0 = __fmaf_rn(v0.w * v0.w, __log2f(1.0f - v0.w), t0);
        float t1 =          (v1.x * v1.x) * __log2f(1.0f - v1.x);
        t1 = __fmaf_rn(v1.y * v1.y, __log2f(1.0f - v1.y), t1);
        t1 = __fmaf_rn(v1.z * v1.z, __log2f(1.0f - v1.z), t1);
        t1 = __fmaf_rn(v1.w * v1.w, __log2f(1.0f - v1.w), t1);
        float t2 =          (v2.x * v2.x) * __log2f(1.0f - v2.x);
        t2 = __fmaf_rn(v2.y * v2.y, __log2f(1.0f - v2.y), t2);
        t2 = __fmaf_rn(v2.z * v2.z, __log2f(1.0f - v2.z), t2);
        t2 = __fmaf_rn(v2.w * v2.w, __log2f(1.0f - v2.w), t2);
        float t3 =          (v3.x * v3.x) * __log2f(1.0f - v3.x);
        t3 = __fmaf_rn(v3.y * v3.y, __log2f(1.0f - v3.y), t3);
        t3 = __fmaf_rn(v3.z * v3.z, __log2f(1.0f - v3.z), t3);
        t3 = __fmaf_rn(v3.w * v3.w, __log2f(1.0f - v3.w), t3);
        neg_acc = __fmaf_rn(m0, t0, neg_acc);
        neg_acc = __fmaf_rn(m1, t1, neg_acc);
        neg_acc = __fmaf_rn(m2, t2, neg_acc);
        neg_acc = __fmaf_rn(m3, t3, neg_acc);
    }

    float local = pos_fix + NEG_SCALE * neg_acc;

    // ---- merged block reduction: (cls local, reg_s, pos_c) in one pass ----
    int lane = threadIdx.x & 31;
    int wid  = threadIdx.x >> 5;
    #pragma unroll
    for (int o = 16; o > 0; o >>= 1) {
        local += __shfl_down_sync(0xFFFFFFFFu, local, o);
        reg_s += __shfl_down_sync(0xFFFFFFFFu, reg_s, o);
        pos_c += __shfl_down_sync(0xFFFFFFFFu, pos_c, o);
    }
    if (lane == 0) { s_wcls[wid] = local; s_wreg[wid] = reg_s; s_wcnt[wid] = pos_c; }
    __syncthreads();
    if (wid == 0) {
        float vc = (lane < (FUS_THREADS / 32)) ? s_wcls[lane] : 0.0f;
        float vr = (lane < (FUS_THREADS / 32)) ? s_wreg[lane] : 0.0f;
        int   vp = (lane < (FUS_THREADS / 32)) ? s_wcnt[lane] : 0;
        #pragma unroll
        for (int o = 8; o > 0; o >>= 1) {
            vc += __shfl_down_sync(0xFFFFFFFFu, vc, o);
            vr += __shfl_down_sync(0xFFFFFFFFu, vr, o);
            vp += __shfl_down_sync(0xFFFFFFFFu, vp, o);
        }
        if (lane == 0) {
            atomicAdd(&g_cls_sum[b], (double)vc);
            if (vp > 0) {
                atomicAdd(&g_reg_sum[b], (double)vr);
                atomicAdd(&g_num_pos[b], vp);
            }
        }
    }

    // ---- finalize: last block computes outputs and resets state ----
    __shared__ int is_last;
    if (threadIdx.x == 0) {
        __threadfence();
        int tkt = atomicAdd(&g_done, 1);
        is_last = (tkt == FUS_BLOCKS - 1);
    }
    __syncthreads();
    if (is_last && wid == 0) {
        __threadfence();   // acquire: see all blocks' atomics
        float cl = 0.0f, rl = 0.0f;
        if (lane < B_NUM) {
            float np = (float)g_num_pos[lane];
            cl = (float)(g_cls_sum[lane]) / fmaxf(np, 1.0f);
            rl = (np > 0.0f)
                   ? (float)(g_reg_sum[lane]) / fmaxf(4.0f * np, 1.0f)
                   : 0.0f;
        }
        #pragma unroll
        for (int o = 4; o > 0; o >>= 1) {
            cl += __shfl_down_sync(0xFFFFFFFFu, cl, o);
            rl += __shfl_down_sync(0xFFFFFFFFu, rl, o);
        }
        if (lane == 0) {
            if (out_size >= 1) out[0] = cl / (float)B_NUM;
            if (out_size >= 2) out[1] = rl / (float)B_NUM;
        }
        // reset accumulators for the next replay
        if (lane < B_NUM) {
            g_cls_sum[lane] = 0.0;
            g_reg_sum[lane] = 0.0;
            g_num_pos[lane] = 0;
        }
        if (lane == 0) g_done = 0;
    }
}

extern "C" void kernel_launch(void* const* d_in, const int* in_sizes, int n_in,
                              void* d_out, int out_size) {
    const float* classifications = (const float*)d_in[0];
    const float* regressions     = (const float*)d_in[1];
    const float* anchors         = (const float*)d_in[2];
    const float* annotations     = (const float*)d_in[3];
    float* out = (float*)d_out;

    dim3 fgrid(A_NUM / FUS_APB, B_NUM);   // 375 x 8 = 3000 blocks
    fused_kernel<<<fgrid, FUS_THREADS>>>(classifications, regressions,
                                         anchors, annotations, out, out_size);
}